// round 5
// baseline (speedup 1.0000x reference)
#include <cuda_runtime.h>
#include <cstdint>
#include <cstddef>

#define Bsz 8
#define Cc  32
#define Oo  64
#define Hh  64
#define Ww  64
#define Kk  9

constexpr int OTILE = 8;                  // o's per block
constexpr int SEG   = Ww * Kk;            // 576 floats per (o,c,h)
constexpr int WTILE = OTILE * SEG;        // 4608 floats per c
constexpr int XROWS = 3;
constexpr int XCOLP = 72;                 // [3]=col -1, [4..67]=cols 0..63, [68]=col 64
constexpr int XTILE = Bsz * XROWS * XCOLP;// 1728 floats per c
constexpr int SMEM_BYTES = (2 * WTILE + 2 * XTILE) * 4;  // 50688 B -> 4 CTAs/SM
constexpr int WC_STRIDE = Hh * SEG;       // weight float-offset advance per channel
constexpr int XC_STRIDE = Hh * Ww;        // x float-offset advance per channel

__device__ __forceinline__ void cp16(float* dst_smem, const float* src, int sz) {
    uint32_t a = (uint32_t)__cvta_generic_to_shared(dst_smem);
    asm volatile("cp.async.cg.shared.global [%0], [%1], 16, %2;"
                 :: "r"(a), "l"(src), "r"(sz));
}

__global__ void __launch_bounds__(128, 4)
lc2d_kernel(const float* __restrict__ x,
            const float* __restrict__ wt,
            float* __restrict__ out)
{
    extern __shared__ float smem[];
    float* wsm = smem;                    // [2][WTILE]
    float* xsm = smem + 2 * WTILE;        // [2][XTILE]

    const int tx = threadIdx.x;           // 128 threads
    const int w  = tx & 63;
    const int oq = tx >> 6;               // 0..1
    const int h  = blockIdx.x;
    const int ob = blockIdx.y * OTILE;
    const int o0 = ob + oq * 4;

    // one-time halo zeros (cols 3 and 68 of every row, both buffers).
    // cp.async below only ever writes floats [4..67] of each row, so these persist.
    if (tx < 96) {
        int bufsel = tx / 48;
        int t      = tx - bufsel * 48;
        int b      = t / 6;
        int q      = t - b * 6;
        int r      = q >> 1;
        int side   = q & 1;
        xsm[bufsel * XTILE + (b * XROWS + r) * XCOLP + (side ? 68 : 3)] = 0.f;
    }

    // ---- per-thread loop-invariant staging descriptors (marching gmem offsets) ----
    int  wgo[9];
    int  wso[9];
    #pragma unroll
    for (int i = 0; i < 9; i++) {
        int idx = tx + i * 128;
        int seg = idx / 144;
        int pos = idx - seg * 144;
        wgo[i] = (((ob + seg) * Cc) * Hh + h) * SEG + pos * 4;
        wso[i] = seg * SEG + pos * 4;
    }
    int  xgo[3];
    int  xso[3];
    int  xsz[3];
    #pragma unroll
    for (int i = 0; i < 3; i++) {
        int idx = tx + i * 128;
        int b   = idx / 48;
        int rem = idx - b * 48;
        int r   = rem >> 4;
        int j   = rem & 15;
        int grow = h - 1 + r;
        xsz[i]  = (grow >= 0 && grow < Hh) ? 16 : 0;
        int gr  = grow < 0 ? 0 : (grow > Hh - 1 ? Hh - 1 : grow);
        xgo[i]  = ((b * Cc) * Hh + gr) * Ww + j * 4;
        xso[i]  = (b * XROWS + r) * XCOLP + 4 + j * 4;
    }

    float acc[4][Bsz];
    #pragma unroll
    for (int oo = 0; oo < 4; oo++)
        #pragma unroll
        for (int b = 0; b < Bsz; b++)
            acc[oo][b] = 0.f;

    auto stage = [&](int buf) {   // stages current wgo/xgo (one channel), advances them
        float* wb = wsm + buf * WTILE;
        #pragma unroll
        for (int i = 0; i < 9; i++) {
            cp16(wb + wso[i], wt + wgo[i], 16);
            wgo[i] += WC_STRIDE;
        }
        float* xb = xsm + buf * XTILE;
        #pragma unroll
        for (int i = 0; i < 3; i++) {
            cp16(xb + xso[i], x + xgo[i], xsz[i]);
            xgo[i] += XC_STRIDE;
        }
    };

    // ---- prologue: two stages in flight (depth-2 pipeline) ----
    stage(0);
    asm volatile("cp.async.commit_group;");
    stage(1);
    asm volatile("cp.async.commit_group;");

    #pragma unroll 2
    for (int c = 0; c < Cc; c++) {
        const int cur = c & 1;
        // stage(c) was committed two stages back: allow stage(c+1) to remain pending
        asm volatile("cp.async.wait_group 1;");
        __syncthreads();                       // stage(c) visible to all threads

        // weights for 4 o's: conflict-free scalar LDS (lane stride 9 vs 32 banks)
        const float* wb = wsm + cur * WTILE + oq * 4 * SEG + w * Kk;
        float wr[4][Kk];
        #pragma unroll
        for (int oo = 0; oo < 4; oo++) {
            #pragma unroll
            for (int k = 0; k < Kk; k++)
                wr[oo][k] = wb[oo * SEG + k];
        }

        const float* xp = xsm + cur * XTILE + 3 + w;
        #pragma unroll
        for (int b = 0; b < Bsz; b++) {
            float xv[9];
            #pragma unroll
            for (int r = 0; r < 3; r++) {
                xv[r * 3 + 0] = xp[r * XCOLP + 0];
                xv[r * 3 + 1] = xp[r * XCOLP + 1];
                xv[r * 3 + 2] = xp[r * XCOLP + 2];
            }
            #pragma unroll
            for (int oo = 0; oo < 4; oo++)
                #pragma unroll
                for (int k = 0; k < Kk; k++)
                    acc[oo][b] = fmaf(wr[oo][k], xv[k], acc[oo][b]);
            xp += XROWS * XCOLP;
        }

        __syncthreads();                       // all warps done READING buf `cur`
        if (c + 2 < Cc)
            stage(cur);                        // refill the buffer just consumed
        asm volatile("cp.async.commit_group;");// (possibly empty) keeps group FIFO uniform
    }

    float* op = out + ((size_t)o0 * Hh + h) * Ww + w;
    #pragma unroll
    for (int b = 0; b < Bsz; b++)
        #pragma unroll
        for (int oo = 0; oo < 4; oo++)
            op[(size_t)(b * Oo + oo) * (Hh * Ww)] = acc[oo][b];
}

extern "C" void kernel_launch(void* const* d_in, const int* in_sizes, int n_in,
                              void* d_out, int out_size)
{
    const float* x  = (const float*)d_in[0];
    const float* wt = (const float*)d_in[1];
    float* out      = (float*)d_out;

    cudaFuncSetAttribute(lc2d_kernel,
                         cudaFuncAttributeMaxDynamicSharedMemorySize, SMEM_BYTES);

    dim3 grid(Hh, Oo / OTILE);   // 64 x 8 = 512 blocks of 128 threads
    lc2d_kernel<<<grid, 128, SMEM_BYTES>>>(x, wt, out);
}